// round 1
// baseline (speedup 1.0000x reference)
#include <cuda_runtime.h>
#include <math.h>

#define DEV __device__ __forceinline__

constexpr int Bn   = 256;
constexpr int Rimg = 36;
constexpr int Lcap = 32;
constexpr int Dm   = 1024;
constexpr int ROWS_IMG = Bn * Rimg;   // 9216
constexpr int ROWS_CAP = Bn * Lcap;   // 8192

// ---------------- device scratch (no allocations allowed) ----------------
__device__ float g_imgN[ROWS_IMG * Dm];
__device__ float g_capN[ROWS_CAP * Dm];
__device__ float g_imgP[ROWS_IMG * Dm];
__device__ float g_capP[ROWS_CAP * Dm];
__device__ float g_colmax[Bn * ROWS_IMG];      // reused by both calls (serial stream)
__device__ float g_tv1[Bn * 3];
__device__ int   g_ti1[Bn * 3];
__device__ float g_tv2[Bn * 3];
__device__ int   g_ti2[Bn * 3];
__device__ float g_m2k1[Bn * 3];
__device__ float g_m2k2[Bn * 3];

// ---------------- packed fp32x2 helpers (Blackwell FFMA2) ----------------
DEV unsigned long long pack2(float x) {
    unsigned long long r;
    asm("mov.b64 %0, {%1, %1};" : "=l"(r) : "f"(x));
    return r;
}
DEV void fma2(unsigned long long& d, unsigned long long a, unsigned long long b) {
    asm("fma.rn.f32x2 %0, %1, %2, %0;" : "+l"(d) : "l"(a), "l"(b));
}
DEV void unpack2(unsigned long long v, float& lo, float& hi) {
    asm("mov.b64 {%0, %1}, %2;" : "=f"(lo), "=f"(hi) : "l"(v));
}

// ---------------- L2-normalize rows of [nrows, 1024] ----------------
__global__ void norm_kernel(const float* __restrict__ in, float* __restrict__ out, int nrows) {
    int warp = (blockIdx.x * blockDim.x + threadIdx.x) >> 5;
    int lane = threadIdx.x & 31;
    if (warp >= nrows) return;
    const float4* src = reinterpret_cast<const float4*>(in + (size_t)warp * Dm);
    float4* dst       = reinterpret_cast<float4*>(out + (size_t)warp * Dm);
    float4 v[8];
    float ss = 0.f;
#pragma unroll
    for (int i = 0; i < 8; i++) {
        v[i] = src[lane + 32 * i];
        ss += v[i].x * v[i].x + v[i].y * v[i].y + v[i].z * v[i].z + v[i].w * v[i].w;
    }
#pragma unroll
    for (int o = 16; o > 0; o >>= 1) ss += __shfl_xor_sync(0xffffffffu, ss, o);
    float nrm = fmaxf(sqrtf(ss), 1e-8f);
    float inv = 1.0f / nrm;
#pragma unroll
    for (int i = 0; i < 8; i++) {
        float4 w = v[i];
        w.x *= inv; w.y *= inv; w.z *= inv; w.w *= inv;
        dst[lane + 32 * i] = w;
    }
}

// ---------------- phase-1: per-column max over one n's R rows -------------
// A: [Bn*R, 1024]  (n-major),  Bmat: [CT, 1024]  (flattened (p,l) rows)
// colmax[n][col] = max_{r<R} dot(A[n*R+r], Bmat[col])
// Block: 2 n-groups (2R rows) x 128 cols. KC=32 smem chunks, f32x2 FMA.
template <int R>
__global__ void sim_colmax_kernel(const float* __restrict__ A,
                                  const float* __restrict__ Bmat,
                                  float* __restrict__ colmax, int CT) {
    constexpr int ROWS = 2 * R;
    constexpr int TR = (R == 36) ? 6 : 4;
    constexpr int NTY = ROWS / TR;          // 12 or 16
    constexpr int NTX = 16;
    constexpr int TC = 8;
    constexpr int COLS = 128;
    constexpr int KC = 32;
    constexpr int THREADS = NTX * NTY;      // 192 or 256
    constexpr int ASTR = ROWS + 1;          // 73 / 65 (odd -> conflict-free stores)
    constexpr int BSTR = 132;               // 16B-aligned rows for LDS.64

    __shared__ __align__(16) float As[KC][ASTR];
    __shared__ __align__(16) float Bs[KC][BSTR];

    const int tid = threadIdx.x;
    const int tx = tid % NTX;
    const int ty = tid / NTX;

    const float* Ab = A + (size_t)blockIdx.y * ROWS * Dm;
    const float* Bb = Bmat + (size_t)blockIdx.x * COLS * Dm;

    unsigned long long acc[TR][TC / 2];
#pragma unroll
    for (int i = 0; i < TR; i++)
#pragma unroll
        for (int j = 0; j < TC / 2; j++) acc[i][j] = 0ull;

    for (int k0 = 0; k0 < Dm; k0 += KC) {
        __syncthreads();
        for (int idx = tid; idx < ROWS * KC; idx += THREADS) {
            int r = idx >> 5, kk = idx & 31;
            As[kk][r] = Ab[(size_t)r * Dm + k0 + kk];
        }
        for (int idx = tid; idx < COLS * KC; idx += THREADS) {
            int c = idx >> 5, kk = idx & 31;
            Bs[kk][c] = Bb[(size_t)c * Dm + k0 + kk];
        }
        __syncthreads();
#pragma unroll 8
        for (int kk = 0; kk < KC; kk++) {
            unsigned long long a2[TR];
#pragma unroll
            for (int i = 0; i < TR; i++) a2[i] = pack2(As[kk][ty * TR + i]);
            const unsigned long long* bp =
                reinterpret_cast<const unsigned long long*>(&Bs[kk][tx * TC]);
            unsigned long long b2[TC / 2];
#pragma unroll
            for (int j = 0; j < TC / 2; j++) b2[j] = bp[j];
#pragma unroll
            for (int i = 0; i < TR; i++)
#pragma unroll
                for (int j = 0; j < TC / 2; j++) fma2(acc[i][j], a2[i], b2[j]);
        }
    }

    // thread-local column maxes over its TR rows (all within one n-group)
    float cmax[TC];
#pragma unroll
    for (int j = 0; j < TC; j++) cmax[j] = -INFINITY;
#pragma unroll
    for (int i = 0; i < TR; i++)
#pragma unroll
        for (int j = 0; j < TC / 2; j++) {
            float lo, hi;
            unpack2(acc[i][j], lo, hi);
            cmax[2 * j]     = fmaxf(cmax[2 * j], lo);
            cmax[2 * j + 1] = fmaxf(cmax[2 * j + 1], hi);
        }
    __syncthreads();
    float* pm = &Bs[0][0];  // NTY x COLS partials (reuses Bs)
#pragma unroll
    for (int j = 0; j < TC; j++) pm[ty * COLS + tx * TC + j] = cmax[j];
    __syncthreads();
    for (int c = tid; c < COLS; c += THREADS) {
        float m0 = -INFINITY, m1 = -INFINITY;
#pragma unroll
        for (int t = 0; t < NTY / 2; t++) m0 = fmaxf(m0, pm[t * COLS + c]);
#pragma unroll
        for (int t = NTY / 2; t < NTY; t++) m1 = fmaxf(m1, pm[t * COLS + c]);
        size_t n0 = (size_t)blockIdx.y * 2;
        size_t cg = (size_t)blockIdx.x * COLS + c;
        colmax[n0 * CT + cg]       = m0;
        colmax[(n0 + 1) * CT + cg] = m1;
    }
}

// ---------------- sim row = sum of L colmax values; then top-3 ------------
template <int L>
__global__ void sim_top3_kernel(const float* __restrict__ colmax, int CT,
                                float* __restrict__ tv, int* __restrict__ ti) {
    const int n = blockIdx.x;
    const int t = threadIdx.x;  // 256 threads == 256 candidate p's
    const float* row = colmax + (size_t)n * CT + (size_t)t * L;
    float s = 0.f;
#pragma unroll
    for (int l = 0; l < L; l++) s += row[l];
    __shared__ float sv[256];
    __shared__ float rv[256];
    __shared__ int ri[256];
    sv[t] = s;
    __syncthreads();
    for (int k = 0; k < 3; k++) {
        rv[t] = sv[t];
        ri[t] = t;
        __syncthreads();
        for (int off = 128; off > 0; off >>= 1) {
            if (t < off) {
                float v2 = rv[t + off];
                int i2 = ri[t + off];
                if (v2 > rv[t] || (v2 == rv[t] && i2 < ri[t])) { rv[t] = v2; ri[t] = i2; }
            }
            __syncthreads();
        }
        if (t == 0) {
            tv[n * 3 + k] = rv[0];
            ti[n * 3 + k] = ri[0];
            sv[ri[0]] = -INFINITY;   // mask and repeat (jax tie-break: smaller idx)
        }
        __syncthreads();
    }
}

// ---------------- phase-2: m2k[n,k] = sum_l max_r dot(A[n,r], B[idx,l]) ---
template <int R2, int L2>
__global__ void p2_kernel(const float* __restrict__ A, const float* __restrict__ Bmat,
                          const int* __restrict__ ti, float* __restrict__ m2k) {
    constexpr int TR = (R2 == 36) ? 3 : 4;
    constexpr int NTY = R2 / TR;            // 12 or 8
    constexpr int TC = (L2 == 36) ? 3 : 4;
    constexpr int NTX = L2 / TC;            // 12 or 8
    constexpr int THREADS = NTX * NTY;      // 96
    constexpr int KC = 32;

    __shared__ float As[KC][R2 + 1];
    __shared__ float Bs[KC][37];
    __shared__ float pm[NTY * L2];
    __shared__ float cm[L2];

    const int nk = blockIdx.x;
    const int nrow = nk / 3;
    const int tid = threadIdx.x;
    const int tx = tid % NTX;
    const int ty = tid / NTX;
    const int p = ti[nk];

    const float* Ab = A + (size_t)nrow * R2 * Dm;
    const float* Bb = Bmat + (size_t)p * L2 * Dm;

    float acc[TR][TC];
#pragma unroll
    for (int i = 0; i < TR; i++)
#pragma unroll
        for (int j = 0; j < TC; j++) acc[i][j] = 0.f;

    for (int k0 = 0; k0 < Dm; k0 += KC) {
        __syncthreads();
        for (int idx = tid; idx < R2 * KC; idx += THREADS) {
            int r = idx >> 5, kk = idx & 31;
            As[kk][r] = Ab[(size_t)r * Dm + k0 + kk];
        }
        for (int idx = tid; idx < L2 * KC; idx += THREADS) {
            int c = idx >> 5, kk = idx & 31;
            Bs[kk][c] = Bb[(size_t)c * Dm + k0 + kk];
        }
        __syncthreads();
#pragma unroll 8
        for (int kk = 0; kk < KC; kk++) {
            float a[TR], b[TC];
#pragma unroll
            for (int i = 0; i < TR; i++) a[i] = As[kk][ty * TR + i];
#pragma unroll
            for (int j = 0; j < TC; j++) b[j] = Bs[kk][tx * TC + j];
#pragma unroll
            for (int i = 0; i < TR; i++)
#pragma unroll
                for (int j = 0; j < TC; j++) acc[i][j] = fmaf(a[i], b[j], acc[i][j]);
        }
    }

    float cmax[TC];
#pragma unroll
    for (int j = 0; j < TC; j++) {
        cmax[j] = -INFINITY;
#pragma unroll
        for (int i = 0; i < TR; i++) cmax[j] = fmaxf(cmax[j], acc[i][j]);
    }
    __syncthreads();
#pragma unroll
    for (int j = 0; j < TC; j++) pm[ty * L2 + tx * TC + j] = cmax[j];
    __syncthreads();
    if (tid < L2) {
        float m = -INFINITY;
#pragma unroll
        for (int t = 0; t < NTY; t++) m = fmaxf(m, pm[t * L2 + tid]);
        cm[tid] = m;
    }
    __syncthreads();
    if (tid == 0) {
        float s = 0.f;
        for (int c = 0; c < L2; c++) s += cm[c];
        m2k[nk] = s;
    }
}

// ---------------- final KL reduction --------------------------------------
__global__ void kl_kernel(const float* __restrict__ tv1, const float* __restrict__ m2k1,
                          const float* __restrict__ tv2, const float* __restrict__ m2k2,
                          float* __restrict__ out) {
    const int t = threadIdx.x;  // 512: 256 rows per call
    const float* a = (t < 256) ? (tv1 + t * 3) : (tv2 + (t - 256) * 3);
    const float* b = (t < 256) ? (m2k1 + t * 3) : (m2k2 + (t - 256) * 3);
    float x[3], y[3];
#pragma unroll
    for (int i = 0; i < 3; i++) { x[i] = a[i] / 3.0f; y[i] = b[i] / 3.0f; }
    float mx = fmaxf(x[0], fmaxf(x[1], x[2]));
    float my = fmaxf(y[0], fmaxf(y[1], y[2]));
    float sx = expf(x[0] - mx) + expf(x[1] - mx) + expf(x[2] - mx);
    float sy = expf(y[0] - my) + expf(y[1] - my) + expf(y[2] - my);
    float lsex = mx + logf(sx);
    float lsey = my + logf(sy);
    double local = 0.0;
#pragma unroll
    for (int i = 0; i < 3; i++) {
        float lp = x[i] - lsex;
        float lq = y[i] - lsey;
        local += (double)expf(lp) * (double)(lp - lq);
    }
    __shared__ double red[512];
    red[t] = local;
    __syncthreads();
    for (int off = 256; off > 0; off >>= 1) {
        if (t < off) red[t] += red[t + off];
        __syncthreads();
    }
    if (t == 0) out[0] = (float)red[0];
}

// ---------------- launcher -------------------------------------------------
extern "C" void kernel_launch(void* const* d_in, const int* in_sizes, int n_in,
                              void* d_out, int out_size) {
    const float* imgN_in = (const float*)d_in[0];
    const float* capN_in = (const float*)d_in[1];
    const float* imgP_in = (const float*)d_in[2];
    const float* capP_in = (const float*)d_in[3];
    float* out = (float*)d_out;

    float *imgN, *capN, *imgP, *capP, *cmx, *tv1, *tv2, *m2k1, *m2k2;
    int *ti1, *ti2;
    cudaGetSymbolAddress((void**)&imgN, g_imgN);
    cudaGetSymbolAddress((void**)&capN, g_capN);
    cudaGetSymbolAddress((void**)&imgP, g_imgP);
    cudaGetSymbolAddress((void**)&capP, g_capP);
    cudaGetSymbolAddress((void**)&cmx,  g_colmax);
    cudaGetSymbolAddress((void**)&tv1,  g_tv1);
    cudaGetSymbolAddress((void**)&ti1,  g_ti1);
    cudaGetSymbolAddress((void**)&tv2,  g_tv2);
    cudaGetSymbolAddress((void**)&ti2,  g_ti2);
    cudaGetSymbolAddress((void**)&m2k1, g_m2k1);
    cudaGetSymbolAddress((void**)&m2k2, g_m2k2);

    norm_kernel<<<(ROWS_IMG + 7) / 8, 256>>>(imgN_in, imgN, ROWS_IMG);
    norm_kernel<<<(ROWS_CAP + 7) / 8, 256>>>(capN_in, capN, ROWS_CAP);
    norm_kernel<<<(ROWS_IMG + 7) / 8, 256>>>(imgP_in, imgP, ROWS_IMG);
    norm_kernel<<<(ROWS_CAP + 7) / 8, 256>>>(capP_in, capP, ROWS_CAP);

    // ---- call 1: STL(img_n, img_p, cap_p): R=36, L=36, phase2 L2=32 ----
    {
        dim3 grid(ROWS_IMG / 128, Bn / 2);
        sim_colmax_kernel<36><<<grid, 192>>>(imgN, imgP, cmx, ROWS_IMG);
        sim_top3_kernel<36><<<Bn, 256>>>(cmx, ROWS_IMG, tv1, ti1);
        p2_kernel<36, 32><<<Bn * 3, 96>>>(imgN, capP, ti1, m2k1);
    }
    // ---- call 2: STL(cap_n, cap_p, img_p): R=32, L=32, phase2 L2=36 ----
    {
        dim3 grid(ROWS_CAP / 128, Bn / 2);
        sim_colmax_kernel<32><<<grid, 256>>>(capN, capP, cmx, ROWS_CAP);
        sim_top3_kernel<32><<<Bn, 256>>>(cmx, ROWS_CAP, tv2, ti2);
        p2_kernel<32, 36><<<Bn * 3, 96>>>(capN, imgP, ti2, m2k2);
    }

    kl_kernel<<<1, 512>>>(tv1, m2k1, tv2, m2k2, out);
}

// round 3
// speedup vs baseline: 2.9875x; 2.9875x over previous
#include <cuda_runtime.h>
#include <cuda_bf16.h>
#include <math.h>

#define DEV __device__ __forceinline__

constexpr int Bn   = 256;
constexpr int Rimg = 36;
constexpr int Lcap = 32;
constexpr int Dm   = 1024;
constexpr int ROWS_IMG = Bn * Rimg;   // 9216
constexpr int ROWS_CAP = Bn * Lcap;   // 8192

// GEMM tiling
constexpr int TM = 256;
constexpr int TN = 128;
constexpr int KS = 32;                 // K per stage
constexpr int KSE = 40;                // padded k-stride in bf16 elems (80B rows)
constexpr int STG_ELEMS = (TM + TM + TN + TN) * KSE;   // Ahi,Alo,Bhi,Blo = 30720
constexpr int GEMM_SMEM = 2 * STG_ELEMS * 2;           // 122880 bytes

// ---------------- device scratch (no allocations allowed) ----------------
__device__ float g_imgN[ROWS_IMG * Dm];
__device__ float g_capN[ROWS_CAP * Dm];
__device__ float g_imgP[ROWS_IMG * Dm];
__device__ float g_capP[ROWS_CAP * Dm];
__device__ __nv_bfloat16 g_imgN_hi[ROWS_IMG * Dm];
__device__ __nv_bfloat16 g_imgN_lo[ROWS_IMG * Dm];
__device__ __nv_bfloat16 g_capN_hi[ROWS_CAP * Dm];
__device__ __nv_bfloat16 g_capN_lo[ROWS_CAP * Dm];
__device__ __nv_bfloat16 g_imgP_hi[ROWS_IMG * Dm];
__device__ __nv_bfloat16 g_imgP_lo[ROWS_IMG * Dm];
__device__ __nv_bfloat16 g_capP_hi[ROWS_CAP * Dm];
__device__ __nv_bfloat16 g_capP_lo[ROWS_CAP * Dm];
__device__ float g_pcmax[2 * Bn * ROWS_IMG];   // [slot][group n][col]
__device__ float g_tv1[Bn * 3];
__device__ int   g_ti1[Bn * 3];
__device__ float g_tv2[Bn * 3];
__device__ int   g_ti2[Bn * 3];
__device__ float g_m2k1[Bn * 3];
__device__ float g_m2k2[Bn * 3];

// ---------------- helpers ----------------
DEV void cp16(void* smem_dst, const void* gmem_src) {
    unsigned s = (unsigned)__cvta_generic_to_shared(smem_dst);
    asm volatile("cp.async.cg.shared.global [%0], [%1], 16;" :: "r"(s), "l"(gmem_src));
}
#define CP_COMMIT() asm volatile("cp.async.commit_group;")
#define CP_WAIT(n)  asm volatile("cp.async.wait_group %0;" :: "n"(n))

DEV void mma_bf16(float* c, const unsigned* a, unsigned b0, unsigned b1) {
    asm volatile(
        "mma.sync.aligned.m16n8k16.row.col.f32.bf16.bf16.f32 "
        "{%0,%1,%2,%3},{%4,%5,%6,%7},{%8,%9},{%0,%1,%2,%3};"
        : "+f"(c[0]), "+f"(c[1]), "+f"(c[2]), "+f"(c[3])
        : "r"(a[0]), "r"(a[1]), "r"(a[2]), "r"(a[3]), "r"(b0), "r"(b1));
}

// ---------- L2-normalize rows of [nrows,1024]; emit fp32 + bf16 hi/lo ------
__global__ void norm_kernel(const float* __restrict__ in, float* __restrict__ out,
                            __nv_bfloat16* __restrict__ out_hi,
                            __nv_bfloat16* __restrict__ out_lo, int nrows) {
    int warp = (blockIdx.x * blockDim.x + threadIdx.x) >> 5;
    int lane = threadIdx.x & 31;
    if (warp >= nrows) return;
    const float4* src = reinterpret_cast<const float4*>(in + (size_t)warp * Dm);
    float4* dst       = reinterpret_cast<float4*>(out + (size_t)warp * Dm);
    __nv_bfloat16* dh = out_hi + (size_t)warp * Dm;
    __nv_bfloat16* dl = out_lo + (size_t)warp * Dm;
    float4 v[8];
    float ss = 0.f;
#pragma unroll
    for (int i = 0; i < 8; i++) {
        v[i] = src[lane + 32 * i];
        ss += v[i].x * v[i].x + v[i].y * v[i].y + v[i].z * v[i].z + v[i].w * v[i].w;
    }
#pragma unroll
    for (int o = 16; o > 0; o >>= 1) ss += __shfl_xor_sync(0xffffffffu, ss, o);
    float inv = 1.0f / fmaxf(sqrtf(ss), 1e-8f);
#pragma unroll
    for (int i = 0; i < 8; i++) {
        float4 w = v[i];
        w.x *= inv; w.y *= inv; w.z *= inv; w.w *= inv;
        dst[lane + 32 * i] = w;
        float xs[4] = {w.x, w.y, w.z, w.w};
        __nv_bfloat16 h4[4], l4[4];
#pragma unroll
        for (int j = 0; j < 4; j++) {
            __nv_bfloat16 h = __float2bfloat16_rn(xs[j]);
            h4[j] = h;
            l4[j] = __float2bfloat16_rn(xs[j] - __bfloat162float(h));
        }
        *(ushort4*)&dh[(lane + 32 * i) * 4] = *(ushort4*)h4;
        *(ushort4*)&dl[(lane + 32 * i) * 4] = *(ushort4*)l4;
    }
}

// ------- phase-1: 3xbf16 MMA GEMM (fp32-grade) + per-group column max ------
// A rows grouped by n (R rows each); B rows = flattened (p,l).
// pcmax[slot][g][col] = max over this CTA-tile's rows of group g; slot =
// blockIdx.y - firstTile(g); a group spans <=2 M-tiles.
template <int R>
__global__ __launch_bounds__(256, 1)
void gemm_colmax(const __nv_bfloat16* __restrict__ Ahi, const __nv_bfloat16* __restrict__ Alo,
                 const __nv_bfloat16* __restrict__ Bhi, const __nv_bfloat16* __restrict__ Blo,
                 float* __restrict__ pcmax, int CT) {
    extern __shared__ char smch[];
    __nv_bfloat16* sm = reinterpret_cast<__nv_bfloat16*>(smch);

    const int tid  = threadIdx.x;
    const int lane = tid & 31;
    const int wid  = tid >> 5;        // 0..7
    const int g    = lane >> 2;       // 0..7
    const int tig  = lane & 3;        // 0..3
    const int wm   = wid >> 1;        // 0..3  (64-row warp tiles)
    const int wn   = wid & 1;         // 0..1  (64-col warp tiles)

    const __nv_bfloat16* Ah = Ahi + (size_t)blockIdx.y * TM * Dm;
    const __nv_bfloat16* Al = Alo + (size_t)blockIdx.y * TM * Dm;
    const __nv_bfloat16* Bh = Bhi + (size_t)blockIdx.x * TN * Dm;
    const __nv_bfloat16* Bl = Blo + (size_t)blockIdx.x * TN * Dm;

    float c[4][8][4];
#pragma unroll
    for (int mf = 0; mf < 4; mf++)
#pragma unroll
        for (int nf = 0; nf < 8; nf++)
#pragma unroll
            for (int r = 0; r < 4; r++) c[mf][nf][r] = 0.f;

    // stage plane offsets (bf16 elems)
    constexpr int OF_AH = 0;
    constexpr int OF_AL = TM * KSE;
    constexpr int OF_BH = 2 * TM * KSE;
    constexpr int OF_BL = 2 * TM * KSE + TN * KSE;

    auto load_stage = [&](int s, int buf) {
        const int k0 = s * KS;
        __nv_bfloat16* st = sm + buf * STG_ELEMS;
#pragma unroll
        for (int t = 0; t < 4; t++) {   // A planes: 256 rows x 4 granules (8 bf16)
            int idx = tid + t * 256;
            int row = idx >> 2, q = idx & 3;
            cp16(st + OF_AH + row * KSE + q * 8, Ah + (size_t)row * Dm + k0 + q * 8);
            cp16(st + OF_AL + row * KSE + q * 8, Al + (size_t)row * Dm + k0 + q * 8);
        }
#pragma unroll
        for (int t = 0; t < 2; t++) {   // B planes: 128 rows x 4 granules
            int idx = tid + t * 256;
            int row = idx >> 2, q = idx & 3;
            cp16(st + OF_BH + row * KSE + q * 8, Bh + (size_t)row * Dm + k0 + q * 8);
            cp16(st + OF_BL + row * KSE + q * 8, Bl + (size_t)row * Dm + k0 + q * 8);
        }
    };

    load_stage(0, 0);
    CP_COMMIT();

    constexpr int NS = Dm / KS;  // 32
#pragma unroll 1
    for (int s = 0; s < NS; s++) {
        if (s + 1 < NS) {
            load_stage(s + 1, (s + 1) & 1);
            CP_COMMIT();
            CP_WAIT(1);
        } else {
            CP_WAIT(0);
        }
        __syncthreads();

        const __nv_bfloat16* st = sm + (s & 1) * STG_ELEMS;
        const __nv_bfloat16* sAh = st + OF_AH + (size_t)(wm * 64) * KSE;
        const __nv_bfloat16* sAl = st + OF_AL + (size_t)(wm * 64) * KSE;
        const __nv_bfloat16* sBh = st + OF_BH + (size_t)(wn * 64) * KSE;
        const __nv_bfloat16* sBl = st + OF_BL + (size_t)(wn * 64) * KSE;

#pragma unroll
        for (int kk = 0; kk < KS / 16; kk++) {   // 2 k16 steps
            unsigned ah[4][4], al[4][4];
#pragma unroll
            for (int mf = 0; mf < 4; mf++) {
                int base = (mf * 16 + g) * KSE + kk * 16 + 2 * tig;
                ah[mf][0] = *(const unsigned*)&sAh[base];
                ah[mf][1] = *(const unsigned*)&sAh[base + 8 * KSE];
                ah[mf][2] = *(const unsigned*)&sAh[base + 8];
                ah[mf][3] = *(const unsigned*)&sAh[base + 8 * KSE + 8];
                al[mf][0] = *(const unsigned*)&sAl[base];
                al[mf][1] = *(const unsigned*)&sAl[base + 8 * KSE];
                al[mf][2] = *(const unsigned*)&sAl[base + 8];
                al[mf][3] = *(const unsigned*)&sAl[base + 8 * KSE + 8];
            }
#pragma unroll
            for (int nf = 0; nf < 8; nf++) {
                int base = (nf * 8 + g) * KSE + kk * 16 + 2 * tig;
                unsigned bh0 = *(const unsigned*)&sBh[base];
                unsigned bh1 = *(const unsigned*)&sBh[base + 8];
                unsigned bl0 = *(const unsigned*)&sBl[base];
                unsigned bl1 = *(const unsigned*)&sBl[base + 8];
#pragma unroll
                for (int mf = 0; mf < 4; mf++) {
                    mma_bf16(c[mf][nf], ah[mf], bl0, bl1);   // hi*lo'
                    mma_bf16(c[mf][nf], al[mf], bh0, bh1);   // lo*hi'
                    mma_bf16(c[mf][nf], ah[mf], bh0, bh1);   // hi*hi'
                }
            }
        }
        __syncthreads();
    }

    // ---- epilogue: stage 128 rows at a time through smem, reduce per group ----
    float* red = reinterpret_cast<float*>(smch);   // [128][132]
    const int m0 = blockIdx.y * TM;
    int   curg = m0 / R;
    float curv = -INFINITY;
    const int col  = tid & 127;
    const size_t colg = (size_t)blockIdx.x * TN + col;

#pragma unroll 1
    for (int h = 0; h < 2; h++) {
        if ((wm >> 1) == h) {
            const int r0 = (wm - 2 * h) * 64;
#pragma unroll
            for (int mf = 0; mf < 4; mf++)
#pragma unroll
                for (int nf = 0; nf < 8; nf++) {
                    int rr = r0 + mf * 16 + g;
                    int cc = wn * 64 + nf * 8 + 2 * tig;
                    *(float2*)&red[rr * 132 + cc]       = make_float2(c[mf][nf][0], c[mf][nf][1]);
                    *(float2*)&red[(rr + 8) * 132 + cc] = make_float2(c[mf][nf][2], c[mf][nf][3]);
                }
        }
        __syncthreads();
        if (tid < 128) {
            for (int r = 0; r < 128; r++) {
                int grp = (m0 + h * 128 + r) / R;
                float v = red[r * 132 + col];
                if (grp != curg) {
                    int slot = blockIdx.y - (curg * R) / TM;
                    pcmax[(size_t)slot * Bn * CT + (size_t)curg * CT + colg] = curv;
                    curg = grp;
                    curv = v;
                } else {
                    curv = fmaxf(curv, v);
                }
            }
        }
        __syncthreads();
    }
    if (tid < 128) {
        int slot = blockIdx.y - (curg * R) / TM;
        pcmax[(size_t)slot * Bn * CT + (size_t)curg * CT + colg] = curv;
    }
}

// ---------------- sim row = sum of L colmax values; then top-3 ------------
template <int L, int R>
__global__ void sim_top3_kernel(const float* __restrict__ pcmax, int CT,
                                float* __restrict__ tv, int* __restrict__ ti) {
    const int n = blockIdx.x;
    const int t = threadIdx.x;  // 256 candidate p's
    const bool two = ((n * R) / TM) != ((n * R + R - 1) / TM);
    const float* b0 = pcmax + (size_t)n * CT + (size_t)t * L;
    const float* b1 = b0 + (size_t)Bn * CT;
    float s = 0.f;
#pragma unroll
    for (int l = 0; l < L; l++) {
        float v = b0[l];
        if (two) v = fmaxf(v, b1[l]);
        s += v;
    }
    __shared__ float sv[256];
    __shared__ float rv[256];
    __shared__ int ri[256];
    sv[t] = s;
    __syncthreads();
    for (int k = 0; k < 3; k++) {
        rv[t] = sv[t];
        ri[t] = t;
        __syncthreads();
        for (int off = 128; off > 0; off >>= 1) {
            if (t < off) {
                float v2 = rv[t + off];
                int i2 = ri[t + off];
                if (v2 > rv[t] || (v2 == rv[t] && i2 < ri[t])) { rv[t] = v2; ri[t] = i2; }
            }
            __syncthreads();
        }
        if (t == 0) {
            tv[n * 3 + k] = rv[0];
            ti[n * 3 + k] = ri[0];
            sv[ri[0]] = -INFINITY;
        }
        __syncthreads();
    }
}

// ---------------- phase-2: m2k[n,k] = sum_l max_r dot(A[n,r], B[idx,l]) ---
template <int R2, int L2>
__global__ void p2_kernel(const float* __restrict__ A, const float* __restrict__ Bmat,
                          const int* __restrict__ ti, float* __restrict__ m2k) {
    constexpr int TR = (R2 == 36) ? 3 : 4;
    constexpr int NTY = R2 / TR;
    constexpr int TC = (L2 == 36) ? 3 : 4;
    constexpr int NTX = L2 / TC;
    constexpr int THREADS = NTX * NTY;  // 96
    constexpr int KC = 32;

    __shared__ float As[KC][R2 + 1];
    __shared__ float Bs[KC][37];
    __shared__ float pm[NTY * L2];
    __shared__ float cm[L2];

    const int nk = blockIdx.x;
    const int nrow = nk / 3;
    const int tid = threadIdx.x;
    const int tx = tid % NTX;
    const int ty = tid / NTX;
    const int p = ti[nk];

    const float* Ab = A + (size_t)nrow * R2 * Dm;
    const float* Bb = Bmat + (size_t)p * L2 * Dm;

    float acc[TR][TC];
#pragma unroll
    for (int i = 0; i < TR; i++)
#pragma unroll
        for (int j = 0; j < TC; j++) acc[i][j] = 0.f;

    for (int k0 = 0; k0 < Dm; k0 += KC) {
        __syncthreads();
        for (int idx = tid; idx < R2 * KC; idx += THREADS) {
            int r = idx >> 5, kk = idx & 31;
            As[kk][r] = Ab[(size_t)r * Dm + k0 + kk];
        }
        for (int idx = tid; idx < L2 * KC; idx += THREADS) {
            int c2 = idx >> 5, kk = idx & 31;
            Bs[kk][c2] = Bb[(size_t)c2 * Dm + k0 + kk];
        }
        __syncthreads();
#pragma unroll 8
        for (int kk = 0; kk < KC; kk++) {
            float a[TR], b[TC];
#pragma unroll
            for (int i = 0; i < TR; i++) a[i] = As[kk][ty * TR + i];
#pragma unroll
            for (int j = 0; j < TC; j++) b[j] = Bs[kk][tx * TC + j];
#pragma unroll
            for (int i = 0; i < TR; i++)
#pragma unroll
                for (int j = 0; j < TC; j++) acc[i][j] = fmaf(a[i], b[j], acc[i][j]);
        }
    }

    float cmax[TC];
#pragma unroll
    for (int j = 0; j < TC; j++) {
        cmax[j] = -INFINITY;
#pragma unroll
        for (int i = 0; i < TR; i++) cmax[j] = fmaxf(cmax[j], acc[i][j]);
    }
    __syncthreads();
#pragma unroll
    for (int j = 0; j < TC; j++) pm[ty * L2 + tx * TC + j] = cmax[j];
    __syncthreads();
    if (tid < L2) {
        float m = -INFINITY;
#pragma unroll
        for (int t = 0; t < NTY; t++) m = fmaxf(m, pm[t * L2 + tid]);
        cm[tid] = m;
    }
    __syncthreads();
    if (tid == 0) {
        float s = 0.f;
        for (int c2 = 0; c2 < L2; c2++) s += cm[c2];
        m2k[nk] = s;
    }
}

// ---------------- final KL reduction --------------------------------------
__global__ void kl_kernel(const float* __restrict__ tv1, const float* __restrict__ m2k1,
                          const float* __restrict__ tv2, const float* __restrict__ m2k2,
                          float* __restrict__ out) {
    const int t = threadIdx.x;
    const float* a = (t < 256) ? (tv1 + t * 3) : (tv2 + (t - 256) * 3);
    const float* b = (t < 256) ? (m2k1 + t * 3) : (m2k2 + (t - 256) * 3);
    float x[3], y[3];
#pragma unroll
    for (int i = 0; i < 3; i++) { x[i] = a[i] / 3.0f; y[i] = b[i] / 3.0f; }
    float mx = fmaxf(x[0], fmaxf(x[1], x[2]));
    float my = fmaxf(y[0], fmaxf(y[1], y[2]));
    float sx = expf(x[0] - mx) + expf(x[1] - mx) + expf(x[2] - mx);
    float sy = expf(y[0] - my) + expf(y[1] - my) + expf(y[2] - my);
    float lsex = mx + logf(sx);
    float lsey = my + logf(sy);
    double local = 0.0;
#pragma unroll
    for (int i = 0; i < 3; i++) {
        float lp = x[i] - lsex;
        float lq = y[i] - lsey;
        local += (double)expf(lp) * (double)(lp - lq);
    }
    __shared__ double red[512];
    red[t] = local;
    __syncthreads();
    for (int off = 256; off > 0; off >>= 1) {
        if (t < off) red[t] += red[t + off];
        __syncthreads();
    }
    if (t == 0) out[0] = (float)red[0];
}

// ---------------- launcher -------------------------------------------------
extern "C" void kernel_launch(void* const* d_in, const int* in_sizes, int n_in,
                              void* d_out, int out_size) {
    const float* imgN_in = (const float*)d_in[0];
    const float* capN_in = (const float*)d_in[1];
    const float* imgP_in = (const float*)d_in[2];
    const float* capP_in = (const float*)d_in[3];
    float* out = (float*)d_out;

    float *imgN, *capN, *imgP, *capP, *pcm, *tv1, *tv2, *m2k1, *m2k2;
    int *ti1, *ti2;
    __nv_bfloat16 *imgNh, *imgNl, *capNh, *capNl, *imgPh, *imgPl, *capPh, *capPl;
    cudaGetSymbolAddress((void**)&imgN, g_imgN);
    cudaGetSymbolAddress((void**)&capN, g_capN);
    cudaGetSymbolAddress((void**)&imgP, g_imgP);
    cudaGetSymbolAddress((void**)&capP, g_capP);
    cudaGetSymbolAddress((void**)&imgNh, g_imgN_hi);
    cudaGetSymbolAddress((void**)&imgNl, g_imgN_lo);
    cudaGetSymbolAddress((void**)&capNh, g_capN_hi);
    cudaGetSymbolAddress((void**)&capNl, g_capN_lo);
    cudaGetSymbolAddress((void**)&imgPh, g_imgP_hi);
    cudaGetSymbolAddress((void**)&imgPl, g_imgP_lo);
    cudaGetSymbolAddress((void**)&capPh, g_capP_hi);
    cudaGetSymbolAddress((void**)&capPl, g_capP_lo);
    cudaGetSymbolAddress((void**)&pcm,  g_pcmax);
    cudaGetSymbolAddress((void**)&tv1,  g_tv1);
    cudaGetSymbolAddress((void**)&ti1,  g_ti1);
    cudaGetSymbolAddress((void**)&tv2,  g_tv2);
    cudaGetSymbolAddress((void**)&ti2,  g_ti2);
    cudaGetSymbolAddress((void**)&m2k1, g_m2k1);
    cudaGetSymbolAddress((void**)&m2k2, g_m2k2);

    // Opt into >48KB dynamic smem (persistent attribute; skip inside capture).
    cudaStreamCaptureStatus st = cudaStreamCaptureStatusNone;
    cudaStreamIsCapturing(0, &st);
    if (st == cudaStreamCaptureStatusNone) {
        cudaFuncSetAttribute(gemm_colmax<36>, cudaFuncAttributeMaxDynamicSharedMemorySize, GEMM_SMEM);
        cudaFuncSetAttribute(gemm_colmax<32>, cudaFuncAttributeMaxDynamicSharedMemorySize, GEMM_SMEM);
    }

    norm_kernel<<<(ROWS_IMG + 7) / 8, 256>>>(imgN_in, imgN, imgNh, imgNl, ROWS_IMG);
    norm_kernel<<<(ROWS_CAP + 7) / 8, 256>>>(capN_in, capN, capNh, capNl, ROWS_CAP);
    norm_kernel<<<(ROWS_IMG + 7) / 8, 256>>>(imgP_in, imgP, imgPh, imgPl, ROWS_IMG);
    norm_kernel<<<(ROWS_CAP + 7) / 8, 256>>>(capP_in, capP, capPh, capPl, ROWS_CAP);

    // ---- call 1: STL(img_n, img_p, cap_p): R=36, phase2 L2=32 ----
    {
        dim3 grid(ROWS_IMG / TN, ROWS_IMG / TM);   // (72, 36)
        gemm_colmax<36><<<grid, 256, GEMM_SMEM>>>(imgNh, imgNl, imgPh, imgPl, pcm, ROWS_IMG);
        sim_top3_kernel<36, 36><<<Bn, 256>>>(pcm, ROWS_IMG, tv1, ti1);
        p2_kernel<36, 32><<<Bn * 3, 96>>>(imgN, capP, ti1, m2k1);
    }
    // ---- call 2: STL(cap_n, cap_p, img_p): R=32, phase2 L2=36 ----
    {
        dim3 grid(ROWS_CAP / TN, ROWS_CAP / TM);   // (64, 32)
        gemm_colmax<32><<<grid, 256, GEMM_SMEM>>>(capNh, capNl, capPh, capPl, pcm, ROWS_CAP);
        sim_top3_kernel<32, 32><<<Bn, 256>>>(pcm, ROWS_CAP, tv2, ti2);
        p2_kernel<32, 36><<<Bn * 3, 96>>>(capN, imgP, ti2, m2k2);
    }

    kl_kernel<<<1, 512>>>(tv1, m2k1, tv2, m2k2, out);
}

// round 5
// speedup vs baseline: 3.5253x; 1.1800x over previous
#include <cuda_runtime.h>
#include <cuda_bf16.h>
#include <math.h>
#include <stdint.h>

#define DEV __device__ __forceinline__

constexpr int Bn   = 256;
constexpr int Rimg = 36;
constexpr int Lcap = 32;
constexpr int Dm   = 1024;
constexpr int ROWS_IMG = Bn * Rimg;   // 9216
constexpr int ROWS_CAP = Bn * Lcap;   // 8192

// ---- GEMM tiling: CTA 256x128, 512 threads, warp tile 64x32 ----
constexpr int TM = 256;
constexpr int TN = 128;
constexpr int KS = 32;                         // K per stage
constexpr int NSTG = Dm / KS;                  // 32 stages
constexpr int A_PL = TM * KS * 2;              // 16384 B per A plane
constexpr int B_PL = TN * KS * 2;              // 8192 B per B plane
constexpr int STG  = 2 * A_PL + 2 * B_PL;      // 49152 B per stage
constexpr int DYN_SMEM = 3 * STG + 1024;       // 148480 (3-stage ring + align)

// ---------------- device scratch (no allocations allowed) ----------------
__device__ float g_imgN[ROWS_IMG * Dm];
__device__ float g_capN[ROWS_CAP * Dm];
__device__ float g_imgP[ROWS_IMG * Dm];
__device__ float g_capP[ROWS_CAP * Dm];
__device__ __nv_bfloat16 g_imgN_hi[ROWS_IMG * Dm];
__device__ __nv_bfloat16 g_imgN_lo[ROWS_IMG * Dm];
__device__ __nv_bfloat16 g_capN_hi[ROWS_CAP * Dm];
__device__ __nv_bfloat16 g_capN_lo[ROWS_CAP * Dm];
__device__ __nv_bfloat16 g_imgP_hi[ROWS_IMG * Dm];
__device__ __nv_bfloat16 g_imgP_lo[ROWS_IMG * Dm];
__device__ __nv_bfloat16 g_capP_hi[ROWS_CAP * Dm];
__device__ __nv_bfloat16 g_capP_lo[ROWS_CAP * Dm];
__device__ float g_pcmax[2 * Bn * ROWS_IMG];   // [slot][group n][col]
__device__ float g_tv1[Bn * 3];
__device__ int   g_ti1[Bn * 3];
__device__ float g_tv2[Bn * 3];
__device__ int   g_ti2[Bn * 3];
__device__ float g_m2k1[Bn * 3];
__device__ float g_m2k2[Bn * 3];

// ---------------- PTX helpers ----------------
DEV unsigned smem_u32(const void* p) {
    unsigned a;
    asm("{ .reg .u64 t; cvta.to.shared.u64 t, %1; cvt.u32.u64 %0, t; }" : "=r"(a) : "l"(p));
    return a;
}
DEV void cp16u(unsigned smem_dst, const void* gmem_src) {
    asm volatile("cp.async.cg.shared.global [%0], [%1], 16;" :: "r"(smem_dst), "l"(gmem_src));
}
#define CP_COMMIT() asm volatile("cp.async.commit_group;")
#define CP_WAIT(n)  asm volatile("cp.async.wait_group %0;" :: "n"(n) : "memory")

DEV void ldsm4(unsigned* d, unsigned addr) {
    asm volatile("ldmatrix.sync.aligned.m8n8.x4.shared.b16 {%0,%1,%2,%3}, [%4];"
                 : "=r"(d[0]), "=r"(d[1]), "=r"(d[2]), "=r"(d[3]) : "r"(addr));
}
DEV void mma_bf16(float* c, const unsigned* a, unsigned b0, unsigned b1) {
    asm volatile(
        "mma.sync.aligned.m16n8k16.row.col.f32.bf16.bf16.f32 "
        "{%0,%1,%2,%3},{%4,%5,%6,%7},{%8,%9},{%0,%1,%2,%3};"
        : "+f"(c[0]), "+f"(c[1]), "+f"(c[2]), "+f"(c[3])
        : "r"(a[0]), "r"(a[1]), "r"(a[2]), "r"(a[3]), "r"(b0), "r"(b1));
}

// ---------- L2-normalize rows of [nrows,1024]; emit fp32 + bf16 hi/lo ------
__global__ void norm_kernel(const float* __restrict__ in, float* __restrict__ out,
                            __nv_bfloat16* __restrict__ out_hi,
                            __nv_bfloat16* __restrict__ out_lo, int nrows) {
    int warp = (blockIdx.x * blockDim.x + threadIdx.x) >> 5;
    int lane = threadIdx.x & 31;
    if (warp >= nrows) return;
    const float4* src = reinterpret_cast<const float4*>(in + (size_t)warp * Dm);
    float4* dst       = reinterpret_cast<float4*>(out + (size_t)warp * Dm);
    __nv_bfloat16* dh = out_hi + (size_t)warp * Dm;
    __nv_bfloat16* dl = out_lo + (size_t)warp * Dm;
    float4 v[8];
    float ss = 0.f;
#pragma unroll
    for (int i = 0; i < 8; i++) {
        v[i] = src[lane + 32 * i];
        ss += v[i].x * v[i].x + v[i].y * v[i].y + v[i].z * v[i].z + v[i].w * v[i].w;
    }
#pragma unroll
    for (int o = 16; o > 0; o >>= 1) ss += __shfl_xor_sync(0xffffffffu, ss, o);
    float inv = 1.0f / fmaxf(sqrtf(ss), 1e-8f);
#pragma unroll
    for (int i = 0; i < 8; i++) {
        float4 w = v[i];
        w.x *= inv; w.y *= inv; w.z *= inv; w.w *= inv;
        dst[lane + 32 * i] = w;
        float xs[4] = {w.x, w.y, w.z, w.w};
        __nv_bfloat16 h4[4], l4[4];
#pragma unroll
        for (int j = 0; j < 4; j++) {
            __nv_bfloat16 h = __float2bfloat16_rn(xs[j]);
            h4[j] = h;
            l4[j] = __float2bfloat16_rn(xs[j] - __bfloat162float(h));
        }
        *(ushort4*)&dh[(lane + 32 * i) * 4] = *(ushort4*)h4;
        *(ushort4*)&dl[(lane + 32 * i) * 4] = *(ushort4*)l4;
    }
}

// ------- phase-1: 3xbf16 ldmatrix+mma GEMM + per-group column max ----------
// Tile: 256x128, 512 thr, 16 warps (wm=wid/4 rows*64, wn=wid%4 cols*32).
// smem planes per stage: Ahi,Alo (256x32), Bhi,Blo (128x32); 64B rows with
// chunk XOR swizzle: byte = r*64 + ((c ^ ((r>>1)&3))*16).
template <int R>
__global__ __launch_bounds__(512, 1)
void gemm_colmax(const __nv_bfloat16* __restrict__ Ahi, const __nv_bfloat16* __restrict__ Alo,
                 const __nv_bfloat16* __restrict__ Bhi, const __nv_bfloat16* __restrict__ Blo,
                 float* __restrict__ pcmax, int CT) {
    extern __shared__ char dynsm[];
    const int tid  = threadIdx.x;
    const int lane = tid & 31;
    const int wid  = tid >> 5;
    const int wm   = wid >> 2;        // 0..3 -> rows wm*64
    const int wn   = wid & 3;         // 0..3 -> cols wn*32

    const unsigned smb0 = smem_u32(dynsm);
    const unsigned smb  = (smb0 + 1023u) & ~1023u;        // 1KB aligned (XOR-safe)
    char* smp = dynsm + (smb - smb0);

    const __nv_bfloat16* Ah = Ahi + (size_t)blockIdx.y * TM * Dm;
    const __nv_bfloat16* Al = Alo + (size_t)blockIdx.y * TM * Dm;
    const __nv_bfloat16* Bh = Bhi + (size_t)blockIdx.x * TN * Dm;
    const __nv_bfloat16* Bl = Blo + (size_t)blockIdx.x * TN * Dm;

    float c[4][4][4];
#pragma unroll
    for (int mf = 0; mf < 4; mf++)
#pragma unroll
        for (int nf = 0; nf < 4; nf++)
#pragma unroll
            for (int r = 0; r < 4; r++) c[mf][nf][r] = 0.f;

    // ldmatrix lane address components (kk=0; kk=1 => XOR 32)
    const int rAl = lane & 15, hiA = lane >> 4;
    const unsigned offA = (unsigned)((wm * 64 + rAl) * 64 + ((hiA ^ ((rAl >> 1) & 3)) * 16));
    const int nB = ((lane >> 4) & 1) * 8 + (lane & 7), hiB = (lane >> 3) & 1;
    const unsigned offB = (unsigned)((wn * 32 + nB) * 64 + ((hiB ^ ((nB >> 1) & 3)) * 16));

    auto load_stage = [&](int s) {
        const unsigned sb = smb + (unsigned)(s % 3) * STG;
        const int k0 = s * KS;
#pragma unroll
        for (int i = 0; i < 6; i++) {
            int idx = tid + i * 512;
            if (idx < 2048) {                       // A planes: 2 x 1024 chunks
                int pl = idx >> 10, cc = idx & 1023;
                int r = cc >> 2, ch = cc & 3;
                const __nv_bfloat16* src = (pl ? Al : Ah) + (size_t)r * Dm + k0 + ch * 8;
                cp16u(sb + pl * A_PL + r * 64 + ((ch ^ ((r >> 1) & 3)) * 16), src);
            } else {                                // B planes: 2 x 512 chunks
                int t2 = idx - 2048;
                int pl = t2 >> 9, cc = t2 & 511;
                int r = cc >> 2, ch = cc & 3;
                const __nv_bfloat16* src = (pl ? Bl : Bh) + (size_t)r * Dm + k0 + ch * 8;
                cp16u(sb + 2 * A_PL + pl * B_PL + r * 64 + ((ch ^ ((r >> 1) & 3)) * 16), src);
            }
        }
        CP_COMMIT();
    };

    load_stage(0);
    load_stage(1);

#pragma unroll 1
    for (int s = 0; s < NSTG; s++) {
        if (s < NSTG - 1) { CP_WAIT(1); } else { CP_WAIT(0); }
        __syncthreads();

        const unsigned sb  = smb + (unsigned)(s % 3) * STG;
        const unsigned aAh = sb + offA;
        const unsigned aAl = sb + A_PL + offA;
        const unsigned aBh = sb + 2 * A_PL + offB;
        const unsigned aBl = sb + 2 * A_PL + B_PL + offB;

#pragma unroll
        for (int kk = 0; kk < 2; kk++) {
            const unsigned kx = kk * 32;
            unsigned bh[2][4], bl[2][4], af[4][4];
#pragma unroll
            for (int j = 0; j < 2; j++) {
                ldsm4(bh[j], (aBh + j * 1024) ^ kx);
                ldsm4(bl[j], (aBl + j * 1024) ^ kx);
            }
#pragma unroll
            for (int mf = 0; mf < 4; mf++) ldsm4(af[mf], (aAh + mf * 1024) ^ kx);
#pragma unroll
            for (int mf = 0; mf < 4; mf++)
#pragma unroll
                for (int j = 0; j < 2; j++)
#pragma unroll
                    for (int sub = 0; sub < 2; sub++) {
                        int nf = j * 2 + sub;
                        mma_bf16(c[mf][nf], af[mf], bl[j][sub * 2], bl[j][sub * 2 + 1]);
                        mma_bf16(c[mf][nf], af[mf], bh[j][sub * 2], bh[j][sub * 2 + 1]);
                    }
#pragma unroll
            for (int mf = 0; mf < 4; mf++) ldsm4(af[mf], (aAl + mf * 1024) ^ kx);
#pragma unroll
            for (int mf = 0; mf < 4; mf++)
#pragma unroll
                for (int j = 0; j < 2; j++)
#pragma unroll
                    for (int sub = 0; sub < 2; sub++) {
                        int nf = j * 2 + sub;
                        mma_bf16(c[mf][nf], af[mf], bh[j][sub * 2], bh[j][sub * 2 + 1]);
                    }
        }
        if (s + 2 < NSTG) load_stage(s + 2);   // targets third buffer, no sync needed
    }
    __syncthreads();

    // ---- epilogue: all 256 rows -> smem [256][132], per-col group-max scan --
    float* red = reinterpret_cast<float*>(smp);
    {
        const int lr = lane >> 2;          // 0..7
        const int lc = (lane & 3) * 2;
#pragma unroll
        for (int mf = 0; mf < 4; mf++)
#pragma unroll
            for (int nf = 0; nf < 4; nf++) {
                int rr = wm * 64 + mf * 16 + lr;
                int cc = wn * 32 + nf * 8 + lc;
                *(float2*)&red[rr * 132 + cc]       = make_float2(c[mf][nf][0], c[mf][nf][1]);
                *(float2*)&red[(rr + 8) * 132 + cc] = make_float2(c[mf][nf][2], c[mf][nf][3]);
            }
    }
    __syncthreads();
    if (tid < TN) {
        const int m0 = blockIdx.y * TM;
        const int col = tid;
        const size_t colg = (size_t)blockIdx.x * TN + col;
        int   curg = m0 / R;
        float curv = -INFINITY;
#pragma unroll 1
        for (int r = 0; r < TM; r++) {
            int grp = (m0 + r) / R;
            float v = red[r * 132 + col];
            if (grp != curg) {
                int slot = blockIdx.y - (curg * R) / TM;
                pcmax[(size_t)slot * Bn * CT + (size_t)curg * CT + colg] = curv;
                curg = grp;
                curv = v;
            } else {
                curv = fmaxf(curv, v);
            }
        }
        int slot = blockIdx.y - (curg * R) / TM;
        pcmax[(size_t)slot * Bn * CT + (size_t)curg * CT + colg] = curv;
    }
}

// ---------------- sim row = sum of L colmax values; then top-3 ------------
template <int L, int R>
__global__ void sim_top3_kernel(const float* __restrict__ pcmax, int CT,
                                float* __restrict__ tv, int* __restrict__ ti) {
    const int n = blockIdx.x;
    const int t = threadIdx.x;  // 256 candidate p's
    const bool two = ((n * R) / TM) != ((n * R + R - 1) / TM);
    const float* b0 = pcmax + (size_t)n * CT + (size_t)t * L;
    const float* b1 = b0 + (size_t)Bn * CT;
    float s = 0.f;
#pragma unroll
    for (int l = 0; l < L; l++) {
        float v = b0[l];
        if (two) v = fmaxf(v, b1[l]);
        s += v;
    }
    __shared__ float sv[256];
    __shared__ float rv[256];
    __shared__ int ri[256];
    sv[t] = s;
    __syncthreads();
    for (int k = 0; k < 3; k++) {
        rv[t] = sv[t];
        ri[t] = t;
        __syncthreads();
        for (int off = 128; off > 0; off >>= 1) {
            if (t < off) {
                float v2 = rv[t + off];
                int i2 = ri[t + off];
                if (v2 > rv[t] || (v2 == rv[t] && i2 < ri[t])) { rv[t] = v2; ri[t] = i2; }
            }
            __syncthreads();
        }
        if (t == 0) {
            tv[n * 3 + k] = rv[0];
            ti[n * 3 + k] = ri[0];
            sv[ri[0]] = -INFINITY;
        }
        __syncthreads();
    }
}

// ---------------- phase-2: m2k[n,k] = sum_l max_r dot(A[n,r], B[idx,l]) ---
template <int R2, int L2>
__global__ void p2_kernel(const float* __restrict__ A, const float* __restrict__ Bmat,
                          const int* __restrict__ ti, float* __restrict__ m2k) {
    constexpr int TR = (R2 == 36) ? 3 : 4;
    constexpr int NTY = R2 / TR;
    constexpr int TC = (L2 == 36) ? 3 : 4;
    constexpr int NTX = L2 / TC;
    constexpr int THREADS = NTX * NTY;  // 96
    constexpr int KC = 32;

    __shared__ float As[KC][R2 + 1];
    __shared__ float Bs[KC][37];
    __shared__ float pm[NTY * L2];
    __shared__ float cm[L2];

    const int nk = blockIdx.x;
    const int nrow = nk / 3;
    const int tid = threadIdx.x;
    const int tx = tid % NTX;
    const int ty = tid / NTX;
    const int p = ti[nk];

    const float* Ab = A + (size_t)nrow * R2 * Dm;
    const float* Bb = Bmat + (size_t)p * L2 * Dm;

    float acc[TR][TC];
#pragma unroll
    for (int i = 0; i < TR; i++)
#pragma unroll
        for (int j = 0; j < TC; j++) acc[i][j] = 0.f;

    for (int k0 = 0; k0 < Dm; k0 += KC) {
        __syncthreads();
        for (int idx = tid; idx < R2 * KC; idx += THREADS) {
            int r = idx >> 5, kk = idx & 31;
            As[kk][r] = Ab[(size_t)r * Dm + k0 + kk];
        }
        for (int idx = tid; idx < L2 * KC; idx += THREADS) {
            int c2 = idx >> 5, kk = idx & 31;
            Bs[kk][c2] = Bb[(size_t)c2 * Dm + k0 + kk];
        }
        __syncthreads();
#pragma unroll 8
        for (int kk = 0; kk < KC; kk++) {
            float a[TR], b[TC];
#pragma unroll
            for (int i = 0; i < TR; i++) a[i] = As[kk][ty * TR + i];
#pragma unroll
            for (int j = 0; j < TC; j++) b[j] = Bs[kk][tx * TC + j];
#pragma unroll
            for (int i = 0; i < TR; i++)
#pragma unroll
                for (int j = 0; j < TC; j++) acc[i][j] = fmaf(a[i], b[j], acc[i][j]);
        }
    }

    float cmax[TC];
#pragma unroll
    for (int j = 0; j < TC; j++) {
        cmax[j] = -INFINITY;
#pragma unroll
        for (int i = 0; i < TR; i++) cmax[j] = fmaxf(cmax[j], acc[i][j]);
    }
    __syncthreads();
#pragma unroll
    for (int j = 0; j < TC; j++) pm[ty * L2 + tx * TC + j] = cmax[j];
    __syncthreads();
    if (tid < L2) {
        float m = -INFINITY;
#pragma unroll
        for (int t = 0; t < NTY; t++) m = fmaxf(m, pm[t * L2 + tid]);
        cm[tid] = m;
    }
    __syncthreads();
    if (tid == 0) {
        float s = 0.f;
        for (int c2 = 0; c2 < L2; c2++) s += cm[c2];
        m2k[nk] = s;
    }
}

// ---------------- final KL reduction --------------------------------------
__global__ void kl_kernel(const float* __restrict__ tv1, const float* __restrict__ m2k1,
                          const float* __restrict__ tv2, const float* __restrict__ m2k2,
                          float* __restrict__ out) {
    const int t = threadIdx.x;
    const float* a = (t < 256) ? (tv1 + t * 3) : (tv2 + (t - 256) * 3);
    const float* b = (t < 256) ? (m2k1 + t * 3) : (m2k2 + (t - 256) * 3);
    float x[3], y[3];
#pragma unroll
    for (int i = 0; i < 3; i++) { x[i] = a[i] / 3.0f; y[i] = b[i] / 3.0f; }
    float mx = fmaxf(x[0], fmaxf(x[1], x[2]));
    float my = fmaxf(y[0], fmaxf(y[1], y[2]));
    float sx = expf(x[0] - mx) + expf(x[1] - mx) + expf(x[2] - mx);
    float sy = expf(y[0] - my) + expf(y[1] - my) + expf(y[2] - my);
    float lsex = mx + logf(sx);
    float lsey = my + logf(sy);
    double local = 0.0;
#pragma unroll
    for (int i = 0; i < 3; i++) {
        float lp = x[i] - lsex;
        float lq = y[i] - lsey;
        local += (double)expf(lp) * (double)(lp - lq);
    }
    __shared__ double red[512];
    red[t] = local;
    __syncthreads();
    for (int off = 256; off > 0; off >>= 1) {
        if (t < off) red[t] += red[t + off];
        __syncthreads();
    }
    if (t == 0) out[0] = (float)red[0];
}

// ---------------- launcher -------------------------------------------------
extern "C" void kernel_launch(void* const* d_in, const int* in_sizes, int n_in,
                              void* d_out, int out_size) {
    const float* imgN_in = (const float*)d_in[0];
    const float* capN_in = (const float*)d_in[1];
    const float* imgP_in = (const float*)d_in[2];
    const float* capP_in = (const float*)d_in[3];
    float* out = (float*)d_out;

    float *imgN, *capN, *imgP, *capP, *pcm, *tv1, *tv2, *m2k1, *m2k2;
    int *ti1, *ti2;
    __nv_bfloat16 *imgNh, *imgNl, *capNh, *capNl, *imgPh, *imgPl, *capPh, *capPl;
    cudaGetSymbolAddress((void**)&imgN, g_imgN);
    cudaGetSymbolAddress((void**)&capN, g_capN);
    cudaGetSymbolAddress((void**)&imgP, g_imgP);
    cudaGetSymbolAddress((void**)&capP, g_capP);
    cudaGetSymbolAddress((void**)&imgNh, g_imgN_hi);
    cudaGetSymbolAddress((void**)&imgNl, g_imgN_lo);
    cudaGetSymbolAddress((void**)&capNh, g_capN_hi);
    cudaGetSymbolAddress((void**)&capNl, g_capN_lo);
    cudaGetSymbolAddress((void**)&imgPh, g_imgP_hi);
    cudaGetSymbolAddress((void**)&imgPl, g_imgP_lo);
    cudaGetSymbolAddress((void**)&capPh, g_capP_hi);
    cudaGetSymbolAddress((void**)&capPl, g_capP_lo);
    cudaGetSymbolAddress((void**)&pcm,  g_pcmax);
    cudaGetSymbolAddress((void**)&tv1,  g_tv1);
    cudaGetSymbolAddress((void**)&ti1,  g_ti1);
    cudaGetSymbolAddress((void**)&tv2,  g_tv2);
    cudaGetSymbolAddress((void**)&ti2,  g_ti2);
    cudaGetSymbolAddress((void**)&m2k1, g_m2k1);
    cudaGetSymbolAddress((void**)&m2k2, g_m2k2);

    // Opt into >48KB dynamic smem (persistent attribute; skip inside capture).
    cudaStreamCaptureStatus st = cudaStreamCaptureStatusNone;
    cudaStreamIsCapturing(0, &st);
    if (st == cudaStreamCaptureStatusNone) {
        cudaFuncSetAttribute(gemm_colmax<36>, cudaFuncAttributeMaxDynamicSharedMemorySize, DYN_SMEM);
        cudaFuncSetAttribute(gemm_colmax<32>, cudaFuncAttributeMaxDynamicSharedMemorySize, DYN_SMEM);
    }

    norm_kernel<<<(ROWS_IMG + 7) / 8, 256>>>(imgN_in, imgN, imgNh, imgNl, ROWS_IMG);
    norm_kernel<<<(ROWS_CAP + 7) / 8, 256>>>(capN_in, capN, capNh, capNl, ROWS_CAP);
    norm_kernel<<<(ROWS_IMG + 7) / 8, 256>>>(imgP_in, imgP, imgPh, imgPl, ROWS_IMG);
    norm_kernel<<<(ROWS_CAP + 7) / 8, 256>>>(capP_in, capP, capPh, capPl, ROWS_CAP);

    // ---- call 1: STL(img_n, img_p, cap_p): R=36, phase2 L2=32 ----
    {
        dim3 grid(ROWS_IMG / TN, ROWS_IMG / TM);   // (72, 36)
        gemm_colmax<36><<<grid, 512, DYN_SMEM>>>(imgNh, imgNl, imgPh, imgPl, pcm, ROWS_IMG);
        sim_top3_kernel<36, 36><<<Bn, 256>>>(pcm, ROWS_IMG, tv1, ti1);
        p2_kernel<36, 32><<<Bn * 3, 96>>>(imgN, capP, ti1, m2k1);
    }
    // ---- call 2: STL(cap_n, cap_p, img_p): R=32, phase2 L2=36 ----
    {
        dim3 grid(ROWS_CAP / TN, ROWS_CAP / TM);   // (64, 32)
        gemm_colmax<32><<<grid, 512, DYN_SMEM>>>(capNh, capNl, capPh, capPl, pcm, ROWS_CAP);
        sim_top3_kernel<32, 32><<<Bn, 256>>>(pcm, ROWS_CAP, tv2, ti2);
        p2_kernel<32, 36><<<Bn * 3, 96>>>(capN, imgP, ti2, m2k2);
    }

    kl_kernel<<<1, 512>>>(tv1, m2k1, tv2, m2k2, out);
}

// round 6
// speedup vs baseline: 4.7554x; 1.3489x over previous
#include <cuda_runtime.h>
#include <cuda_bf16.h>
#include <math.h>
#include <stdint.h>

#define DEV __device__ __forceinline__

constexpr int Bn   = 256;
constexpr int Rimg = 36;
constexpr int Lcap = 32;
constexpr int Dm   = 1024;
constexpr int ROWS_IMG = Bn * Rimg;   // 9216
constexpr int ROWS_CAP = Bn * Lcap;   // 8192
constexpr int TOPC = 8;               // candidates kept for exact rescoring

// ---- GEMM tiling: CTA 256x128, 512 threads, warp tile 64x32, 1 bf16 plane ----
constexpr int TM = 256;
constexpr int TN = 128;
constexpr int KS = 32;                         // K per stage
constexpr int NSTG = Dm / KS;                  // 32 stages
constexpr int A_PL = TM * KS * 2;              // 16384 B
constexpr int B_PL = TN * KS * 2;              // 8192 B
constexpr int STG  = A_PL + B_PL;              // 24576 B per stage
constexpr int DYN_SMEM = 3 * STG + 1024;       // 74752 (3-stage ring + align)

// ---------------- device scratch (no allocations allowed) ----------------
__device__ float g_imgN[ROWS_IMG * Dm];
__device__ float g_capN[ROWS_CAP * Dm];
__device__ float g_imgP[ROWS_IMG * Dm];
__device__ float g_capP[ROWS_CAP * Dm];
__device__ __nv_bfloat16 g_imgN_hi[ROWS_IMG * Dm];
__device__ __nv_bfloat16 g_capN_hi[ROWS_CAP * Dm];
__device__ __nv_bfloat16 g_imgP_hi[ROWS_IMG * Dm];
__device__ __nv_bfloat16 g_capP_hi[ROWS_CAP * Dm];
__device__ float g_pcmax[2 * Bn * ROWS_IMG];   // [slot][group n][col]
__device__ int   g_ti8a[Bn * TOPC];
__device__ int   g_ti8b[Bn * TOPC];
__device__ float g_sc8a[Bn * TOPC];
__device__ float g_sc8b[Bn * TOPC];
__device__ float g_tv1[Bn * 3];
__device__ int   g_ti1[Bn * 3];
__device__ float g_tv2[Bn * 3];
__device__ int   g_ti2[Bn * 3];
__device__ float g_m2k1[Bn * 3];
__device__ float g_m2k2[Bn * 3];

// ---------------- PTX helpers ----------------
DEV unsigned smem_u32(const void* p) {
    unsigned a;
    asm("{ .reg .u64 t; cvta.to.shared.u64 t, %1; cvt.u32.u64 %0, t; }" : "=r"(a) : "l"(p));
    return a;
}
DEV void cp16u(unsigned smem_dst, const void* gmem_src) {
    asm volatile("cp.async.cg.shared.global [%0], [%1], 16;" :: "r"(smem_dst), "l"(gmem_src));
}
#define CP_COMMIT() asm volatile("cp.async.commit_group;")
#define CP_WAIT(n)  asm volatile("cp.async.wait_group %0;" :: "n"(n) : "memory")

DEV void ldsm4(unsigned* d, unsigned addr) {
    asm volatile("ldmatrix.sync.aligned.m8n8.x4.shared.b16 {%0,%1,%2,%3}, [%4];"
                 : "=r"(d[0]), "=r"(d[1]), "=r"(d[2]), "=r"(d[3]) : "r"(addr));
}
DEV void mma_bf16(float* c, const unsigned* a, unsigned b0, unsigned b1) {
    asm volatile(
        "mma.sync.aligned.m16n8k16.row.col.f32.bf16.bf16.f32 "
        "{%0,%1,%2,%3},{%4,%5,%6,%7},{%8,%9},{%0,%1,%2,%3};"
        : "+f"(c[0]), "+f"(c[1]), "+f"(c[2]), "+f"(c[3])
        : "r"(a[0]), "r"(a[1]), "r"(a[2]), "r"(a[3]), "r"(b0), "r"(b1));
}

// ---------- L2-normalize rows of [nrows,1024]; emit fp32 + bf16 ------------
__global__ void norm_kernel(const float* __restrict__ in, float* __restrict__ out,
                            __nv_bfloat16* __restrict__ out_hi, int nrows) {
    int warp = (blockIdx.x * blockDim.x + threadIdx.x) >> 5;
    int lane = threadIdx.x & 31;
    if (warp >= nrows) return;
    const float4* src = reinterpret_cast<const float4*>(in + (size_t)warp * Dm);
    float4* dst       = reinterpret_cast<float4*>(out + (size_t)warp * Dm);
    __nv_bfloat16* dh = out_hi + (size_t)warp * Dm;
    float4 v[8];
    float ss = 0.f;
#pragma unroll
    for (int i = 0; i < 8; i++) {
        v[i] = src[lane + 32 * i];
        ss += v[i].x * v[i].x + v[i].y * v[i].y + v[i].z * v[i].z + v[i].w * v[i].w;
    }
#pragma unroll
    for (int o = 16; o > 0; o >>= 1) ss += __shfl_xor_sync(0xffffffffu, ss, o);
    float inv = 1.0f / fmaxf(sqrtf(ss), 1e-8f);
#pragma unroll
    for (int i = 0; i < 8; i++) {
        float4 w = v[i];
        w.x *= inv; w.y *= inv; w.z *= inv; w.w *= inv;
        dst[lane + 32 * i] = w;
        __nv_bfloat16 h4[4] = {
            __float2bfloat16_rn(w.x), __float2bfloat16_rn(w.y),
            __float2bfloat16_rn(w.z), __float2bfloat16_rn(w.w) };
        *(ushort4*)&dh[(lane + 32 * i) * 4] = *(ushort4*)h4;
    }
}

// ------- phase-1: 1-pass bf16 GEMM (selection precision) + group colmax ----
template <int R>
__global__ __launch_bounds__(512, 1)
void gemm_colmax(const __nv_bfloat16* __restrict__ Ahi,
                 const __nv_bfloat16* __restrict__ Bhi,
                 float* __restrict__ pcmax, int CT) {
    extern __shared__ char dynsm[];
    const int tid  = threadIdx.x;
    const int lane = tid & 31;
    const int wid  = tid >> 5;
    const int wm   = wid >> 2;        // 0..3 -> rows wm*64
    const int wn   = wid & 3;         // 0..3 -> cols wn*32

    const unsigned smb0 = smem_u32(dynsm);
    const unsigned smb  = (smb0 + 1023u) & ~1023u;
    char* smp = dynsm + (smb - smb0);

    const __nv_bfloat16* Ah = Ahi + (size_t)blockIdx.y * TM * Dm;
    const __nv_bfloat16* Bh = Bhi + (size_t)blockIdx.x * TN * Dm;

    float c[4][4][4];
#pragma unroll
    for (int mf = 0; mf < 4; mf++)
#pragma unroll
        for (int nf = 0; nf < 4; nf++)
#pragma unroll
            for (int r = 0; r < 4; r++) c[mf][nf][r] = 0.f;

    // ldmatrix lane address components (kk=0; kk=1 => XOR 32)
    const int rAl = lane & 15, hiA = lane >> 4;
    const unsigned offA = (unsigned)((wm * 64 + rAl) * 64 + ((hiA ^ ((rAl >> 1) & 3)) * 16));
    const int nB = ((lane >> 4) & 1) * 8 + (lane & 7), hiB = (lane >> 3) & 1;
    const unsigned offB = (unsigned)((wn * 32 + nB) * 64 + ((hiB ^ ((nB >> 1) & 3)) * 16));

    auto load_stage = [&](int s) {
        const unsigned sb = smb + (unsigned)(s % 3) * STG;
        const int k0 = s * KS;
#pragma unroll
        for (int i = 0; i < 3; i++) {
            int idx = tid + i * 512;              // 0..1535
            if (idx < 1024) {                     // A: 256 rows x 4 chunks
                int r = idx >> 2, ch = idx & 3;
                cp16u(sb + r * 64 + ((ch ^ ((r >> 1) & 3)) * 16),
                      Ah + (size_t)r * Dm + k0 + ch * 8);
            } else {                              // B: 128 rows x 4 chunks
                int t2 = idx - 1024;
                int r = t2 >> 2, ch = t2 & 3;
                cp16u(sb + A_PL + r * 64 + ((ch ^ ((r >> 1) & 3)) * 16),
                      Bh + (size_t)r * Dm + k0 + ch * 8);
            }
        }
        CP_COMMIT();
    };

    load_stage(0);
    load_stage(1);

#pragma unroll 1
    for (int s = 0; s < NSTG; s++) {
        if (s < NSTG - 1) { CP_WAIT(1); } else { CP_WAIT(0); }
        __syncthreads();

        const unsigned sb  = smb + (unsigned)(s % 3) * STG;
        const unsigned aAh = sb + offA;
        const unsigned aBh = sb + A_PL + offB;

#pragma unroll
        for (int kk = 0; kk < 2; kk++) {
            const unsigned kx = kk * 32;
            unsigned bh[2][4], af[4][4];
#pragma unroll
            for (int j = 0; j < 2; j++) ldsm4(bh[j], (aBh + j * 1024) ^ kx);
#pragma unroll
            for (int mf = 0; mf < 4; mf++) ldsm4(af[mf], (aAh + mf * 1024) ^ kx);
#pragma unroll
            for (int mf = 0; mf < 4; mf++)
#pragma unroll
                for (int j = 0; j < 2; j++)
#pragma unroll
                    for (int sub = 0; sub < 2; sub++) {
                        int nf = j * 2 + sub;
                        mma_bf16(c[mf][nf], af[mf], bh[j][sub * 2], bh[j][sub * 2 + 1]);
                    }
        }
        if (s + 2 < NSTG) load_stage(s + 2);
    }
    __syncthreads();

    // ---- epilogue: two 128-row halves through smem [128][132] -------------
    float* red = reinterpret_cast<float*>(smp);
    const int m0 = blockIdx.y * TM;
    const int col = tid;                   // only tid<128 scans
    const size_t colg = (size_t)blockIdx.x * TN + (col & 127);
    int   curg = m0 / R;
    float curv = -INFINITY;
    const int lr = lane >> 2;
    const int lc = (lane & 3) * 2;

#pragma unroll 1
    for (int h = 0; h < 2; h++) {
        if ((wm >> 1) == h) {
            const int r0 = (wm & 1) * 64;
#pragma unroll
            for (int mf = 0; mf < 4; mf++)
#pragma unroll
                for (int nf = 0; nf < 4; nf++) {
                    int rr = r0 + mf * 16 + lr;
                    int cc = wn * 32 + nf * 8 + lc;
                    *(float2*)&red[rr * 132 + cc]       = make_float2(c[mf][nf][0], c[mf][nf][1]);
                    *(float2*)&red[(rr + 8) * 132 + cc] = make_float2(c[mf][nf][2], c[mf][nf][3]);
                }
        }
        __syncthreads();
        if (tid < 128) {
#pragma unroll 1
            for (int r = 0; r < 128; r++) {
                int grp = (m0 + h * 128 + r) / R;
                float v = red[r * 132 + col];
                if (grp != curg) {
                    int slot = blockIdx.y - (curg * R) / TM;
                    pcmax[(size_t)slot * Bn * CT + (size_t)curg * CT + colg] = curv;
                    curg = grp;
                    curv = v;
                } else {
                    curv = fmaxf(curv, v);
                }
            }
        }
        __syncthreads();
    }
    if (tid < 128) {
        int slot = blockIdx.y - (curg * R) / TM;
        pcmax[(size_t)slot * Bn * CT + (size_t)curg * CT + colg] = curv;
    }
}

// ------- approximate sim row-sum + top-8 candidate selection ---------------
template <int L, int R>
__global__ void sim_top8_kernel(const float* __restrict__ pcmax, int CT,
                                int* __restrict__ ti8) {
    const int n = blockIdx.x;
    const int t = threadIdx.x;  // 256 candidate p's
    const bool two = ((n * R) / TM) != ((n * R + R - 1) / TM);
    const float* b0 = pcmax + (size_t)n * CT + (size_t)t * L;
    const float* b1 = b0 + (size_t)Bn * CT;
    float s = 0.f;
#pragma unroll
    for (int l = 0; l < L; l++) {
        float v = b0[l];
        if (two) v = fmaxf(v, b1[l]);
        s += v;
    }
    __shared__ float sv[256];
    __shared__ float rv[256];
    __shared__ int ri[256];
    sv[t] = s;
    __syncthreads();
    for (int k = 0; k < TOPC; k++) {
        rv[t] = sv[t];
        ri[t] = t;
        __syncthreads();
        for (int off = 128; off > 0; off >>= 1) {
            if (t < off) {
                float v2 = rv[t + off];
                int i2 = ri[t + off];
                if (v2 > rv[t] || (v2 == rv[t] && i2 < ri[t])) { rv[t] = v2; ri[t] = i2; }
            }
            __syncthreads();
        }
        if (t == 0) {
            ti8[n * TOPC + k] = ri[0];
            sv[ri[0]] = -INFINITY;
        }
        __syncthreads();
    }
}

// ---- exact fp32 score: out[nk] = sum_l max_r dot(A[n,r], B[idx[nk],l]) ----
// KPER = candidates per row (8 for rescore, 3 for phase-2).
template <int R2, int L2, int KPER>
__global__ void score_kernel(const float* __restrict__ A, const float* __restrict__ Bmat,
                             const int* __restrict__ ti, float* __restrict__ outv) {
    constexpr int TR = (R2 % 3 == 0) ? 3 : 4;
    constexpr int NTY = R2 / TR;
    constexpr int TC = (L2 % 3 == 0) ? 3 : 4;
    constexpr int NTX = L2 / TC;
    constexpr int THREADS = NTX * NTY;
    constexpr int KC = 32;

    __shared__ float As[KC][R2 + 1];
    __shared__ float Bs[KC][L2 + 1];
    __shared__ float pm[NTY * L2];
    __shared__ float cm[L2];

    const int nk = blockIdx.x;
    const int nrow = nk / KPER;
    const int tid = threadIdx.x;
    const int tx = tid % NTX;
    const int ty = tid / NTX;
    const int p = ti[nk];

    const float* Ab = A + (size_t)nrow * R2 * Dm;
    const float* Bb = Bmat + (size_t)p * L2 * Dm;

    float acc[TR][TC];
#pragma unroll
    for (int i = 0; i < TR; i++)
#pragma unroll
        for (int j = 0; j < TC; j++) acc[i][j] = 0.f;

    for (int k0 = 0; k0 < Dm; k0 += KC) {
        __syncthreads();
        for (int idx = tid; idx < R2 * KC; idx += THREADS) {
            int r = idx >> 5, kk = idx & 31;
            As[kk][r] = Ab[(size_t)r * Dm + k0 + kk];
        }
        for (int idx = tid; idx < L2 * KC; idx += THREADS) {
            int c2 = idx >> 5, kk = idx & 31;
            Bs[kk][c2] = Bb[(size_t)c2 * Dm + k0 + kk];
        }
        __syncthreads();
        float cacc[TR][TC];   // chunk-local accumulation (shorter fp32 chains)
#pragma unroll
        for (int i = 0; i < TR; i++)
#pragma unroll
            for (int j = 0; j < TC; j++) cacc[i][j] = 0.f;
#pragma unroll 8
        for (int kk = 0; kk < KC; kk++) {
            float a[TR], b[TC];
#pragma unroll
            for (int i = 0; i < TR; i++) a[i] = As[kk][ty * TR + i];
#pragma unroll
            for (int j = 0; j < TC; j++) b[j] = Bs[kk][tx * TC + j];
#pragma unroll
            for (int i = 0; i < TR; i++)
#pragma unroll
                for (int j = 0; j < TC; j++) cacc[i][j] = fmaf(a[i], b[j], cacc[i][j]);
        }
#pragma unroll
        for (int i = 0; i < TR; i++)
#pragma unroll
            for (int j = 0; j < TC; j++) acc[i][j] += cacc[i][j];
    }

    float cmax[TC];
#pragma unroll
    for (int j = 0; j < TC; j++) {
        cmax[j] = -INFINITY;
#pragma unroll
        for (int i = 0; i < TR; i++) cmax[j] = fmaxf(cmax[j], acc[i][j]);
    }
    __syncthreads();
#pragma unroll
    for (int j = 0; j < TC; j++) pm[ty * L2 + tx * TC + j] = cmax[j];
    __syncthreads();
    if (tid < L2) {
        float m = -INFINITY;
#pragma unroll
        for (int t = 0; t < NTY; t++) m = fmaxf(m, pm[t * L2 + tid]);
        cm[tid] = m;
    }
    __syncthreads();
    if (tid == 0) {
        float s = 0.f;
        for (int c2 = 0; c2 < L2; c2++) s += cm[c2];
        outv[nk] = s;
    }
}

// ---- exact top-3 of the 8 rescored candidates (jax tie-break: low idx) ----
__global__ void top3_of8_kernel(const float* __restrict__ sc8, const int* __restrict__ ti8,
                                float* __restrict__ tv, int* __restrict__ ti) {
    const int n = blockIdx.x;
    if (threadIdx.x != 0) return;
    float v[TOPC]; int id[TOPC];
#pragma unroll
    for (int j = 0; j < TOPC; j++) { v[j] = sc8[n * TOPC + j]; id[j] = ti8[n * TOPC + j]; }
    for (int k = 0; k < 3; k++) {
        int best = k;
        for (int j = k + 1; j < TOPC; j++)
            if (v[j] > v[best] || (v[j] == v[best] && id[j] < id[best])) best = j;
        float tvv = v[k]; v[k] = v[best]; v[best] = tvv;
        int tii = id[k]; id[k] = id[best]; id[best] = tii;
        tv[n * 3 + k] = v[k];
        ti[n * 3 + k] = id[k];
    }
}

// ---------------- final KL reduction --------------------------------------
__global__ void kl_kernel(const float* __restrict__ tv1, const float* __restrict__ m2k1,
                          const float* __restrict__ tv2, const float* __restrict__ m2k2,
                          float* __restrict__ out) {
    const int t = threadIdx.x;
    const float* a = (t < 256) ? (tv1 + t * 3) : (tv2 + (t - 256) * 3);
    const float* b = (t < 256) ? (m2k1 + t * 3) : (m2k2 + (t - 256) * 3);
    float x[3], y[3];
#pragma unroll
    for (int i = 0; i < 3; i++) { x[i] = a[i] / 3.0f; y[i] = b[i] / 3.0f; }
    float mx = fmaxf(x[0], fmaxf(x[1], x[2]));
    float my = fmaxf(y[0], fmaxf(y[1], y[2]));
    float sx = expf(x[0] - mx) + expf(x[1] - mx) + expf(x[2] - mx);
    float sy = expf(y[0] - my) + expf(y[1] - my) + expf(y[2] - my);
    float lsex = mx + logf(sx);
    float lsey = my + logf(sy);
    double local = 0.0;
#pragma unroll
    for (int i = 0; i < 3; i++) {
        float lp = x[i] - lsex;
        float lq = y[i] - lsey;
        local += (double)expf(lp) * (double)(lp - lq);
    }
    __shared__ double red[512];
    red[t] = local;
    __syncthreads();
    for (int off = 256; off > 0; off >>= 1) {
        if (t < off) red[t] += red[t + off];
        __syncthreads();
    }
    if (t == 0) out[0] = (float)red[0];
}

// ---------------- launcher -------------------------------------------------
extern "C" void kernel_launch(void* const* d_in, const int* in_sizes, int n_in,
                              void* d_out, int out_size) {
    const float* imgN_in = (const float*)d_in[0];
    const float* capN_in = (const float*)d_in[1];
    const float* imgP_in = (const float*)d_in[2];
    const float* capP_in = (const float*)d_in[3];
    float* out = (float*)d_out;

    float *imgN, *capN, *imgP, *capP, *pcm, *tv1, *tv2, *m2k1, *m2k2, *sc8a, *sc8b;
    int *ti1, *ti2, *ti8a, *ti8b;
    __nv_bfloat16 *imgNh, *capNh, *imgPh, *capPh;
    cudaGetSymbolAddress((void**)&imgN, g_imgN);
    cudaGetSymbolAddress((void**)&capN, g_capN);
    cudaGetSymbolAddress((void**)&imgP, g_imgP);
    cudaGetSymbolAddress((void**)&capP, g_capP);
    cudaGetSymbolAddress((void**)&imgNh, g_imgN_hi);
    cudaGetSymbolAddress((void**)&capNh, g_capN_hi);
    cudaGetSymbolAddress((void**)&imgPh, g_imgP_hi);
    cudaGetSymbolAddress((void**)&capPh, g_capP_hi);
    cudaGetSymbolAddress((void**)&pcm,  g_pcmax);
    cudaGetSymbolAddress((void**)&ti8a, g_ti8a);
    cudaGetSymbolAddress((void**)&ti8b, g_ti8b);
    cudaGetSymbolAddress((void**)&sc8a, g_sc8a);
    cudaGetSymbolAddress((void**)&sc8b, g_sc8b);
    cudaGetSymbolAddress((void**)&tv1,  g_tv1);
    cudaGetSymbolAddress((void**)&ti1,  g_ti1);
    cudaGetSymbolAddress((void**)&tv2,  g_tv2);
    cudaGetSymbolAddress((void**)&ti2,  g_ti2);
    cudaGetSymbolAddress((void**)&m2k1, g_m2k1);
    cudaGetSymbolAddress((void**)&m2k2, g_m2k2);

    // Opt into >48KB dynamic smem (persistent attribute; skip inside capture).
    cudaStreamCaptureStatus st = cudaStreamCaptureStatusNone;
    cudaStreamIsCapturing(0, &st);
    if (st == cudaStreamCaptureStatusNone) {
        cudaFuncSetAttribute(gemm_colmax<36>, cudaFuncAttributeMaxDynamicSharedMemorySize, DYN_SMEM);
        cudaFuncSetAttribute(gemm_colmax<32>, cudaFuncAttributeMaxDynamicSharedMemorySize, DYN_SMEM);
    }

    norm_kernel<<<(ROWS_IMG + 7) / 8, 256>>>(imgN_in, imgN, imgNh, ROWS_IMG);
    norm_kernel<<<(ROWS_CAP + 7) / 8, 256>>>(capN_in, capN, capNh, ROWS_CAP);
    norm_kernel<<<(ROWS_IMG + 7) / 8, 256>>>(imgP_in, imgP, imgPh, ROWS_IMG);
    norm_kernel<<<(ROWS_CAP + 7) / 8, 256>>>(capP_in, capP, capPh, ROWS_CAP);

    // ---- call 1: STL(img_n, img_p, cap_p): R=36, L=36, phase2 L2=32 ----
    {
        dim3 grid(ROWS_IMG / TN, ROWS_IMG / TM);   // (72, 36)
        gemm_colmax<36><<<grid, 512, DYN_SMEM>>>(imgNh, imgPh, pcm, ROWS_IMG);
        sim_top8_kernel<36, 36><<<Bn, 256>>>(pcm, ROWS_IMG, ti8a);
        score_kernel<36, 36, TOPC><<<Bn * TOPC, 144>>>(imgN, imgP, ti8a, sc8a);
        top3_of8_kernel<<<Bn, 32>>>(sc8a, ti8a, tv1, ti1);
        score_kernel<36, 32, 3><<<Bn * 3, 96>>>(imgN, capP, ti1, m2k1);
    }
    // ---- call 2: STL(cap_n, cap_p, img_p): R=32, L=32, phase2 L2=36 ----
    {
        dim3 grid(ROWS_CAP / TN, ROWS_CAP / TM);   // (64, 32)
        gemm_colmax<32><<<grid, 512, DYN_SMEM>>>(capNh, capPh, pcm, ROWS_CAP);
        sim_top8_kernel<32, 32><<<Bn, 256>>>(pcm, ROWS_CAP, ti8b);
        score_kernel<32, 32, TOPC><<<Bn * TOPC, 64>>>(capN, capP, ti8b, sc8b);
        top3_of8_kernel<<<Bn, 32>>>(sc8b, ti8b, tv2, ti2);
        score_kernel<32, 36, 3><<<Bn * 3, 96>>>(capN, imgP, ti2, m2k2);
    }

    kl_kernel<<<1, 512>>>(tv1, m2k1, tv2, m2k2, out);
}